// round 6
// baseline (speedup 1.0000x reference)
#include <cuda_runtime.h>
#include <cuda_fp16.h>
#include <cstdint>

// ---------------- problem constants ----------------
#define E_      32768
#define N0_     (15 * E_)
#define NTILES_ 2048                  // 262144 MLP rows / 128
#define NE_OLD_ 1114112
#define NE_NEW_ 2097152
#define NE_TOT_ (NE_OLD_ + NE_NEW_)
#define NNODES_ (31 * E_)

#define EI_OFF_ ((size_t)NNODES_ * 64)
#define EA_OFF_ (EI_OFF_ + 2ull * NE_TOT_)
#define EV_OFF_ (EA_OFF_ + (size_t)NE_TOT_)

// ---------------- smem layout (bytes) ----------------
#define TILE_B  34816                 // 128 rows x 272 B (136 fp16, padded)
#define SM_A    0
#define SM_W1   (SM_A + TILE_B)       // 34816  : 2 halves [h][128n][272B]
#define SM_W2   (SM_W1 + 2 * TILE_B)  // 104448 : 2 halves [kh][128n][272B]
#define SM_H    (SM_W2 + 2 * TILE_B)  // 174080 : hidden tile 128r x 128k (+pad)
#define SM_B1   (SM_H + TILE_B)       // 208896 : 256 floats
#define SM_B2   (SM_B1 + 1024)        // 209920 : 128 floats
#define SM_SZ   (SM_B2 + 512)         // 210432

// ---------------- PTX helpers (base ISA only) ----------------
__device__ __forceinline__ uint32_t smem_u32(const void* p) {
    uint32_t a;
    asm("{ .reg .u64 t; cvta.to.shared.u64 t, %1; cvt.u32.u64 %0, t; }" : "=r"(a) : "l"(p));
    return a;
}

#define CPA16(dst, src) asm volatile("cp.async.cg.shared.global [%0], [%1], 16;" :: "r"(dst), "l"(src) : "memory")
#define CPA_COMMIT()    asm volatile("cp.async.commit_group;" ::: "memory")
#define CPA_WAIT(n)     asm volatile("cp.async.wait_group %0;" :: "n"(n) : "memory")

#define LDSM4(r0, r1, r2, r3, a)                                                   \
    asm volatile("ldmatrix.sync.aligned.m8n8.x4.shared.b16 {%0,%1,%2,%3}, [%4];"   \
        : "=r"(r0), "=r"(r1), "=r"(r2), "=r"(r3) : "r"(a))

#define MMA_F16(d, a0, a1, a2, a3, b0, b1)                                         \
    asm volatile("mma.sync.aligned.m16n8k16.row.col.f32.f16.f16.f32 "              \
        "{%0,%1,%2,%3}, {%4,%5,%6,%7}, {%8,%9}, {%0,%1,%2,%3};"                    \
        : "+f"((d)[0]), "+f"((d)[1]), "+f"((d)[2]), "+f"((d)[3])                   \
        : "r"(a0), "r"(a1), "r"(a2), "r"(a3), "r"(b0), "r"(b1))

__device__ __forceinline__ uint32_t h2u(__half2 h) {
    return *reinterpret_cast<uint32_t*>(&h);
}

// ---------------- pre-padded fp16 weight images + work ticket ----------------
__device__ __align__(16) unsigned char glW1[2 * TILE_B];  // [h][128n][272B]
__device__ __align__(16) unsigned char glW2[2 * TILE_B];  // [kh][128n][272B]
__device__ int g_ticket;

__global__ void prep_w1_kernel(const float* __restrict__ W1) {
    if (blockIdx.x == 0 && threadIdx.x == 0) g_ticket = 0;
    int i = blockIdx.x * blockDim.x + threadIdx.x;
    if (i >= 256 * 128) return;
    int n = i >> 7, k = i & 127;
    uint32_t off = (uint32_t)(n >> 7) * TILE_B + (uint32_t)(n & 127) * 272u + (uint32_t)k * 2u;
    *(__half*)(glW1 + off) = __float2half(W1[k * 256 + n]);
}
__global__ void prep_w2_kernel(const float* __restrict__ W2) {
    int i = blockIdx.x * blockDim.x + threadIdx.x;
    if (i >= 128 * 256) return;
    int n = i >> 8, k = i & 255;
    uint32_t off = (uint32_t)(k >> 7) * TILE_B + (uint32_t)n * 272u + (uint32_t)(k & 127) * 2u;
    *(__half*)(glW2 + off) = __float2half(W2[k * 128 + n]);
}

// build one 128-row A tile (fp16, padded rows). event(row 7E+m) == m mod E.
__device__ __forceinline__ void build_A(unsigned char* Abuf, int m0,
                                        const float* __restrict__ x,
                                        const float* __restrict__ g, int t)
{
    const int r = t >> 1, half = t & 1;
    const int m = m0 + r;
    const float4* src = (half == 0)
        ? (const float4*)(x + ((size_t)(7 * E_) + (size_t)m) * 64)
        : (const float4*)(g + (size_t)(m & (E_ - 1)) * 64);
    unsigned char* Ah = Abuf + (size_t)r * 272 + (size_t)half * 128;
    #pragma unroll
    for (int i = 0; i < 16; i++) {
        float4 v = src[i];
        uint32_t u0 = h2u(__float22half2_rn(make_float2(v.x, v.y)));
        uint32_t u1 = h2u(__float22half2_rn(make_float2(v.z, v.w)));
        *(uint2*)(Ah + i * 8) = make_uint2(u0, u1);
    }
}

// ---------------- persistent fused MLP: 32x64 warp tiles, H staged in smem ----------------
__global__ void __launch_bounds__(256, 1)
mlp_mma_kernel(const float* __restrict__ x,
               const float* __restrict__ g,
               const float* __restrict__ b1, const float* __restrict__ b2,
               float* __restrict__ out)
{
    extern __shared__ __align__(128) unsigned char sm[];
    __shared__ int s_tile;

    const int t = threadIdx.x;
    const int wid = t >> 5, l = t & 31;
    const int mg = wid & 3;            // M group: rows [32mg, 32mg+32)
    const int ng = wid >> 2;           // N group: cols [64ng, 64ng+64)
    const uint32_t sb = smem_u32(sm);

    // ---- all weights resident ----
    for (int i = t; i < 4352; i += 256) {
        CPA16(sb + SM_W1 + (uint32_t)i * 16, glW1 + (size_t)i * 16);
        CPA16(sb + SM_W2 + (uint32_t)i * 16, glW2 + (size_t)i * 16);
    }
    CPA_COMMIT();

    ((float*)(sm + SM_B1))[t] = b1[t];
    if (t < 128) ((float*)(sm + SM_B2))[t] = b2[t];

    // fragment base offsets (within a 128x272B tile)
    const uint32_t ldsmOff = (uint32_t)(l & 15) * 272u + (uint32_t)((l >> 4) << 4);
    const uint32_t aBase = sb + SM_A + (uint32_t)(32 * mg) * 272u + ldsmOff;  // A-frags rows 32mg..
    const uint32_t hBase = sb + SM_H + (uint32_t)(32 * mg) * 272u + ldsmOff;  // H-frags rows 32mg..
    const uint32_t bOff  = (uint32_t)(64 * ng) * 272u + ldsmOff;              // B-frags rows 64ng..
    const float* b1s = (const float*)(sm + SM_B1);
    const float* b2s = (const float*)(sm + SM_B2);

    // hidden-store lane geometry
    const int hRow = (l >> 2);            // row within 8-row group
    const int hCol2 = (l & 3) << 1;       // col pair within n8

    CPA_WAIT(0);

    while (true) {
        if (t == 0) s_tile = atomicAdd(&g_ticket, 1);
        __syncthreads();                  // publishes ticket; A safe to overwrite
        const int tile = s_tile;
        if (tile >= NTILES_) break;
        const int m0 = tile << 7;

        build_A(sm + SM_A, m0, x, g, t);
        __syncthreads();                  // A visible

        float c2[64];
        #pragma unroll
        for (int i = 0; i < 64; i++) c2[i] = 0.0f;

        #pragma unroll 1
        for (int h = 0; h < 2; h++) {
            // ---- GEMM1 half h: c1[j(0..7)][f(0..1)][4] over 32 rows x 64 hidden cols ----
            float c1[64];
            #pragma unroll
            for (int i = 0; i < 64; i++) c1[i] = 0.0f;

            const uint32_t w1A = sb + SM_W1 + (uint32_t)h * TILE_B + bOff;
            #pragma unroll 1
            for (int kc = 0; kc < 8; kc++) {
                uint32_t a0, a1, a2, a3, a4, a5, a6, a7;
                LDSM4(a0, a1, a2, a3, aBase + kc * 32);
                LDSM4(a4, a5, a6, a7, aBase + 16u * 272u + kc * 32);
                uint32_t bb[16];
                #pragma unroll
                for (int bi = 0; bi < 4; bi++)
                    LDSM4(bb[4 * bi], bb[4 * bi + 1], bb[4 * bi + 2], bb[4 * bi + 3],
                          w1A + (uint32_t)bi * (16u * 272u) + kc * 32);
                #pragma unroll
                for (int bi = 0; bi < 4; bi++) {
                    MMA_F16(c1 + (2 * bi) * 8,         a0, a1, a2, a3, bb[4 * bi],     bb[4 * bi + 2]);
                    MMA_F16(c1 + (2 * bi) * 8 + 4,     a4, a5, a6, a7, bb[4 * bi],     bb[4 * bi + 2]);
                    MMA_F16(c1 + (2 * bi + 1) * 8,     a0, a1, a2, a3, bb[4 * bi + 1], bb[4 * bi + 3]);
                    MMA_F16(c1 + (2 * bi + 1) * 8 + 4, a4, a5, a6, a7, bb[4 * bi + 1], bb[4 * bi + 3]);
                }
            }

            __syncthreads();              // all GEMM2(h-1) reads of H done
            // ---- convert: relu(c1 + b1) -> fp16 H tile in smem ----
            #pragma unroll
            for (int j = 0; j < 8; j++) {
                const int colh = 64 * ng + 8 * j + hCol2;      // col within half
                const float2 bb1 = *(const float2*)(b1s + 128 * h + colh);
                #pragma unroll
                for (int f = 0; f < 2; f++) {
                    float v0 = fmaxf(c1[j * 8 + f * 4 + 0] + bb1.x, 0.0f);
                    float v1 = fmaxf(c1[j * 8 + f * 4 + 1] + bb1.y, 0.0f);
                    float v2 = fmaxf(c1[j * 8 + f * 4 + 2] + bb1.x, 0.0f);
                    float v3 = fmaxf(c1[j * 8 + f * 4 + 3] + bb1.y, 0.0f);
                    const int rowA = 32 * mg + 16 * f + hRow;
                    unsigned char* hp = sm + SM_H + (size_t)rowA * 272 + (size_t)colh * 2;
                    *(uint32_t*)hp                = h2u(__float22half2_rn(make_float2(v0, v1)));
                    *(uint32_t*)(hp + 8 * 272)    = h2u(__float22half2_rn(make_float2(v2, v3)));
                }
            }
            __syncthreads();              // H visible

            // ---- GEMM2 half h: c2 += H(32 rows x 128k) @ W2[h] (64 out cols) ----
            const uint32_t w2A = sb + SM_W2 + (uint32_t)h * TILE_B + bOff;
            #pragma unroll 1
            for (int kc = 0; kc < 8; kc++) {
                uint32_t a0, a1, a2, a3, a4, a5, a6, a7;
                LDSM4(a0, a1, a2, a3, hBase + kc * 32);
                LDSM4(a4, a5, a6, a7, hBase + 16u * 272u + kc * 32);
                uint32_t bb[16];
                #pragma unroll
                for (int bi = 0; bi < 4; bi++)
                    LDSM4(bb[4 * bi], bb[4 * bi + 1], bb[4 * bi + 2], bb[4 * bi + 3],
                          w2A + (uint32_t)bi * (16u * 272u) + kc * 32);
                #pragma unroll
                for (int bi = 0; bi < 4; bi++) {
                    MMA_F16(c2 + (2 * bi) * 8,         a0, a1, a2, a3, bb[4 * bi],     bb[4 * bi + 2]);
                    MMA_F16(c2 + (2 * bi) * 8 + 4,     a4, a5, a6, a7, bb[4 * bi],     bb[4 * bi + 2]);
                    MMA_F16(c2 + (2 * bi + 1) * 8,     a0, a1, a2, a3, bb[4 * bi + 1], bb[4 * bi + 3]);
                    MMA_F16(c2 + (2 * bi + 1) * 8 + 4, a4, a5, a6, a7, bb[4 * bi + 1], bb[4 * bi + 3]);
                }
            }
        }

        // ---- epilogue: out = c2 + b2; warp writes branch=ng, cols 8j+hCol2 ----
        {
            #pragma unroll
            for (int j = 0; j < 8; j++) {
                const int n0 = 64 * ng + 8 * j + hCol2;       // output col (0..127)
                const int f = n0 & 63;                        // feature within branch
                const float2 bb = *(const float2*)(b2s + n0);
                #pragma unroll
                for (int fr = 0; fr < 2; fr++) {
                    #pragma unroll
                    for (int rr = 0; rr < 2; rr++) {
                        const int m = m0 + 32 * mg + 16 * fr + 8 * rr + hRow;
                        const int p = m >> 15, e = m & (E_ - 1);
                        size_t orow = (size_t)N0_ + ((size_t)p << 16) + 2u * (size_t)e + (size_t)ng;
                        float2 v;
                        v.x = c2[j * 8 + fr * 4 + 2 * rr + 0] + bb.x;
                        v.y = c2[j * 8 + fr * 4 + 2 * rr + 1] + bb.y;
                        *(float2*)(out + orow * 64 + f) = v;
                    }
                }
            }
        }
    }
}

// ---------------- edge / attr / event fills ----------------
__global__ void copy_old_edges_kernel(const int* __restrict__ ei,
                                      const int* __restrict__ ea,
                                      float* __restrict__ out)
{
    int i = blockIdx.x * blockDim.x + threadIdx.x;
    if (i < NE_OLD_) {
        out[EI_OFF_ + i]                   = (float)ei[i];
        out[EI_OFF_ + (size_t)NE_TOT_ + i] = (float)ei[NE_OLD_ + i];
        out[EA_OFF_ + i]                   = (float)ea[i];
    }
}

__global__ void new_edges_kernel(float* __restrict__ out)
{
    int i = blockIdx.x * blockDim.x + threadIdx.x;
    if (i >= NE_NEW_) return;
    int p   = i >> 18;
    int rem = i & 262143;
    int dm1 = rem >> 16;
    int j   = rem & 65535;
    int e   = j & (E_ - 1);
    int anc = E_ * ((8 >> dm1) - 1);
    int src = anc + (p >> dm1) * E_ + e;
    int tgt = N0_ + (p << 16) + j;
    out[EI_OFF_ + NE_OLD_ + i]                   = (float)src;
    out[EI_OFF_ + (size_t)NE_TOT_ + NE_OLD_ + i] = (float)tgt;
    out[EA_OFF_ + NE_OLD_ + i]                   = (float)(dm1 + 1);
}

__global__ void event_kernel(const int* __restrict__ ev, float* __restrict__ out)
{
    int i = blockIdx.x * blockDim.x + threadIdx.x;
    if (i < NNODES_) {
        float v = (i < N0_) ? (float)ev[i] : (float)((i - N0_) & (E_ - 1));
        out[EV_OFF_ + i] = v;
    }
}

// ---------------- launch ----------------
extern "C" void kernel_launch(void* const* d_in, const int* in_sizes, int n_in,
                              void* d_out, int out_size)
{
    const float* x  = (const float*)d_in[0];
    const int*   ei = (const int*)  d_in[1];
    const int*   ea = (const int*)  d_in[2];
    const int*   ev = (const int*)  d_in[3];
    const float* g  = (const float*)d_in[4];
    const float* W1 = (const float*)d_in[5];
    const float* b1 = (const float*)d_in[6];
    const float* W2 = (const float*)d_in[7];
    const float* b2 = (const float*)d_in[8];
    float* out = (float*)d_out;

    static cudaStream_t s_side = nullptr;
    static cudaEvent_t ev_fork = nullptr, ev_join = nullptr;
    if (s_side == nullptr) {
        cudaStreamCreateWithFlags(&s_side, cudaStreamNonBlocking);
        cudaEventCreateWithFlags(&ev_fork, cudaEventDisableTiming);
        cudaEventCreateWithFlags(&ev_join, cudaEventDisableTiming);
    }

    // fork: copy + fills on side stream, concurrent with prep + MLP
    cudaEventRecord(ev_fork, 0);
    cudaStreamWaitEvent(s_side, ev_fork, 0);

    cudaMemcpyAsync(out, x, (size_t)N0_ * 64 * sizeof(float),
                    cudaMemcpyDeviceToDevice, s_side);
    copy_old_edges_kernel<<<(NE_OLD_ + 255) / 256, 256, 0, s_side>>>(ei, ea, out);
    new_edges_kernel<<<(NE_NEW_ + 255) / 256, 256, 0, s_side>>>(out);
    event_kernel<<<(NNODES_ + 255) / 256, 256, 0, s_side>>>(ev, out);
    cudaEventRecord(ev_join, s_side);

    // main stream: weight prep (+ ticket reset) then persistent MLP
    prep_w1_kernel<<<128, 256>>>(W1);
    prep_w2_kernel<<<128, 256>>>(W2);

    cudaFuncSetAttribute(mlp_mma_kernel, cudaFuncAttributeMaxDynamicSharedMemorySize, SM_SZ);
    mlp_mma_kernel<<<152, 256, SM_SZ>>>(x, g, b1, b2, out);

    // join
    cudaStreamWaitEvent(0, ev_join, 0);
}

// round 7
// speedup vs baseline: 1.0174x; 1.0174x over previous
#include <cuda_runtime.h>
#include <cuda_fp16.h>
#include <cstdint>

// ---------------- problem constants ----------------
#define E_      32768
#define N0_     (15 * E_)
#define NTILES_ 2048                  // 262144 MLP rows / 128
#define NE_OLD_ 1114112
#define NE_NEW_ 2097152
#define NE_TOT_ (NE_OLD_ + NE_NEW_)
#define NNODES_ (31 * E_)

#define EI_OFF_ ((size_t)NNODES_ * 64)
#define EA_OFF_ (EI_OFF_ + 2ull * NE_TOT_)
#define EV_OFF_ (EA_OFF_ + (size_t)NE_TOT_)

// ---------------- smem layout (bytes) ----------------
#define TILE_B  34816                 // 128 rows x 272 B (136 fp16, padded)
#define SM_A    0
#define SM_W1   (SM_A + TILE_B)       // 34816  : 2 halves [h][128n][272B]
#define SM_W2   (SM_W1 + 2 * TILE_B)  // 104448 : 2 halves [kh][128n][272B]
#define SM_H    (SM_W2 + 2 * TILE_B)  // 174080 : hidden tile 128r x 128k (+pad)
#define SM_B1   (SM_H + TILE_B)       // 208896 : 256 floats
#define SM_B2   (SM_B1 + 1024)        // 209920 : 128 floats
#define SM_SZ   (SM_B2 + 512)         // 210432

#define NTHREADS 512

// ---------------- PTX helpers (base ISA only) ----------------
__device__ __forceinline__ uint32_t smem_u32(const void* p) {
    uint32_t a;
    asm("{ .reg .u64 t; cvta.to.shared.u64 t, %1; cvt.u32.u64 %0, t; }" : "=r"(a) : "l"(p));
    return a;
}

#define CPA16(dst, src) asm volatile("cp.async.cg.shared.global [%0], [%1], 16;" :: "r"(dst), "l"(src) : "memory")
#define CPA_COMMIT()    asm volatile("cp.async.commit_group;" ::: "memory")
#define CPA_WAIT(n)     asm volatile("cp.async.wait_group %0;" :: "n"(n) : "memory")

#define LDSM4(r0, r1, r2, r3, a)                                                   \
    asm volatile("ldmatrix.sync.aligned.m8n8.x4.shared.b16 {%0,%1,%2,%3}, [%4];"   \
        : "=r"(r0), "=r"(r1), "=r"(r2), "=r"(r3) : "r"(a))

#define MMA_F16(d, a0, a1, a2, a3, b0, b1)                                         \
    asm volatile("mma.sync.aligned.m16n8k16.row.col.f32.f16.f16.f32 "              \
        "{%0,%1,%2,%3}, {%4,%5,%6,%7}, {%8,%9}, {%0,%1,%2,%3};"                    \
        : "+f"((d)[0]), "+f"((d)[1]), "+f"((d)[2]), "+f"((d)[3])                   \
        : "r"(a0), "r"(a1), "r"(a2), "r"(a3), "r"(b0), "r"(b1))

__device__ __forceinline__ uint32_t h2u(__half2 h) {
    return *reinterpret_cast<uint32_t*>(&h);
}

// ---------------- pre-padded fp16 weight images + work ticket ----------------
__device__ __align__(16) unsigned char glW1[2 * TILE_B];  // [h][128n][272B]
__device__ __align__(16) unsigned char glW2[2 * TILE_B];  // [kh][128n][272B]
__device__ int g_ticket;

__global__ void prep_w1_kernel(const float* __restrict__ W1) {
    if (blockIdx.x == 0 && threadIdx.x == 0) g_ticket = 0;
    int i = blockIdx.x * blockDim.x + threadIdx.x;
    if (i >= 256 * 128) return;
    int n = i >> 7, k = i & 127;
    uint32_t off = (uint32_t)(n >> 7) * TILE_B + (uint32_t)(n & 127) * 272u + (uint32_t)k * 2u;
    *(__half*)(glW1 + off) = __float2half(W1[k * 256 + n]);
}
__global__ void prep_w2_kernel(const float* __restrict__ W2) {
    int i = blockIdx.x * blockDim.x + threadIdx.x;
    if (i >= 128 * 256) return;
    int n = i >> 8, k = i & 255;
    uint32_t off = (uint32_t)(k >> 7) * TILE_B + (uint32_t)n * 272u + (uint32_t)(k & 127) * 2u;
    *(__half*)(glW2 + off) = __float2half(W2[k * 128 + n]);
}

// build one 128-row A tile (fp16, padded rows). event(row 7E+m) == m mod E.
// 512 threads: thread handles 32 features of one row.
__device__ __forceinline__ void build_A(unsigned char* Abuf, int m0,
                                        const float* __restrict__ x,
                                        const float* __restrict__ g, int t)
{
    const int r = t >> 2, q = t & 3;
    const int m = m0 + r;
    const float4* src = (q < 2)
        ? (const float4*)(x + ((size_t)(7 * E_) + (size_t)m) * 64 + 32 * q)
        : (const float4*)(g + (size_t)(m & (E_ - 1)) * 64 + 32 * (q - 2));
    unsigned char* Ap = Abuf + (size_t)r * 272 + (size_t)q * 64;
    #pragma unroll
    for (int i = 0; i < 8; i++) {
        float4 v = src[i];
        uint32_t u0 = h2u(__float22half2_rn(make_float2(v.x, v.y)));
        uint32_t u1 = h2u(__float22half2_rn(make_float2(v.z, v.w)));
        *(uint2*)(Ap + i * 8) = make_uint2(u0, u1);
    }
}

// ---------------- persistent fused MLP: 16 warps, 16x64 warp tiles ----------------
__global__ void __launch_bounds__(NTHREADS, 1)
mlp_mma_kernel(const float* __restrict__ x,
               const float* __restrict__ g,
               const float* __restrict__ b1, const float* __restrict__ b2,
               float* __restrict__ out)
{
    extern __shared__ __align__(128) unsigned char sm[];
    __shared__ int s_tile;

    const int t = threadIdx.x;
    const int wid = t >> 5, l = t & 31;
    const int mg = wid & 7;            // M group: rows [16mg, 16mg+16)
    const int ng = wid >> 3;           // N group: cols [64ng, 64ng+64)
    const uint32_t sb = smem_u32(sm);

    // ---- all weights resident ----
    for (int i = t; i < 4352; i += NTHREADS) {
        CPA16(sb + SM_W1 + (uint32_t)i * 16, glW1 + (size_t)i * 16);
        CPA16(sb + SM_W2 + (uint32_t)i * 16, glW2 + (size_t)i * 16);
    }
    CPA_COMMIT();

    if (t < 256) ((float*)(sm + SM_B1))[t] = b1[t];
    else if (t < 384) ((float*)(sm + SM_B2))[t - 256] = b2[t - 256];

    // fragment base offsets (within a 128x272B tile)
    const uint32_t ldsmOff = (uint32_t)(l & 15) * 272u + (uint32_t)((l >> 4) << 4);
    const uint32_t aBase = sb + SM_A + (uint32_t)(16 * mg) * 272u + ldsmOff;
    const uint32_t hBase = sb + SM_H + (uint32_t)(16 * mg) * 272u + ldsmOff;
    const uint32_t bOff  = (uint32_t)(64 * ng) * 272u + ldsmOff;
    const float* b1s = (const float*)(sm + SM_B1);
    const float* b2s = (const float*)(sm + SM_B2);

    const int hRow = (l >> 2);            // accumulator row within 8-row group
    const int hCol2 = (l & 3) << 1;       // col pair within n8

    CPA_WAIT(0);

    while (true) {
        if (t == 0) s_tile = atomicAdd(&g_ticket, 1);
        __syncthreads();                  // publishes ticket; A + H safe to overwrite
        const int tile = s_tile;
        if (tile >= NTILES_) break;
        const int m0 = tile << 7;

        build_A(sm + SM_A, m0, x, g, t);
        __syncthreads();                  // A visible

        float c2[32];
        #pragma unroll
        for (int i = 0; i < 32; i++) c2[i] = 0.0f;

        #pragma unroll 1
        for (int h = 0; h < 2; h++) {
            // ---- GEMM1 half h: 16 rows x 64 hidden cols, K=128 ----
            float c1[32];
            #pragma unroll
            for (int i = 0; i < 32; i++) c1[i] = 0.0f;

            const uint32_t w1A = sb + SM_W1 + (uint32_t)h * TILE_B + bOff;
            #pragma unroll 1
            for (int kc = 0; kc < 8; kc++) {
                uint32_t a0, a1, a2, a3;
                LDSM4(a0, a1, a2, a3, aBase + kc * 32);
                uint32_t bb[16];
                #pragma unroll
                for (int bi = 0; bi < 4; bi++)
                    LDSM4(bb[4 * bi], bb[4 * bi + 1], bb[4 * bi + 2], bb[4 * bi + 3],
                          w1A + (uint32_t)bi * (16u * 272u) + kc * 32);
                #pragma unroll
                for (int bi = 0; bi < 4; bi++) {
                    MMA_F16(c1 + (2 * bi) * 4,     a0, a1, a2, a3, bb[4 * bi],     bb[4 * bi + 2]);
                    MMA_F16(c1 + (2 * bi + 1) * 4, a0, a1, a2, a3, bb[4 * bi + 1], bb[4 * bi + 3]);
                }
            }

            __syncthreads();              // previous GEMM2 reads of H done
            // ---- convert: relu(c1 + b1) -> fp16 H tile in smem ----
            #pragma unroll
            for (int j = 0; j < 8; j++) {
                const int colh = 64 * ng + 8 * j + hCol2;      // col within half
                const float2 bb1 = *(const float2*)(b1s + 128 * h + colh);
                float v0 = fmaxf(c1[j * 4 + 0] + bb1.x, 0.0f);
                float v1 = fmaxf(c1[j * 4 + 1] + bb1.y, 0.0f);
                float v2 = fmaxf(c1[j * 4 + 2] + bb1.x, 0.0f);
                float v3 = fmaxf(c1[j * 4 + 3] + bb1.y, 0.0f);
                unsigned char* hp = sm + SM_H + (size_t)(16 * mg + hRow) * 272 + (size_t)colh * 2;
                *(uint32_t*)hp             = h2u(__float22half2_rn(make_float2(v0, v1)));
                *(uint32_t*)(hp + 8 * 272) = h2u(__float22half2_rn(make_float2(v2, v3)));
            }
            __syncthreads();              // H visible

            // ---- GEMM2 half h: c2 += H(16r x 128k) @ W2[h] (64 out cols) ----
            const uint32_t w2A = sb + SM_W2 + (uint32_t)h * TILE_B + bOff;
            #pragma unroll 1
            for (int kc = 0; kc < 8; kc++) {
                uint32_t a0, a1, a2, a3;
                LDSM4(a0, a1, a2, a3, hBase + kc * 32);
                uint32_t bb[16];
                #pragma unroll
                for (int bi = 0; bi < 4; bi++)
                    LDSM4(bb[4 * bi], bb[4 * bi + 1], bb[4 * bi + 2], bb[4 * bi + 3],
                          w2A + (uint32_t)bi * (16u * 272u) + kc * 32);
                #pragma unroll
                for (int bi = 0; bi < 4; bi++) {
                    MMA_F16(c2 + (2 * bi) * 4,     a0, a1, a2, a3, bb[4 * bi],     bb[4 * bi + 2]);
                    MMA_F16(c2 + (2 * bi + 1) * 4, a0, a1, a2, a3, bb[4 * bi + 1], bb[4 * bi + 3]);
                }
            }
        }

        // ---- epilogue: out = c2 + b2; warp writes branch=ng ----
        {
            #pragma unroll
            for (int j = 0; j < 8; j++) {
                const int n0 = 64 * ng + 8 * j + hCol2;       // output col (0..127)
                const int f = n0 & 63;                        // feature within branch
                const float2 bb = *(const float2*)(b2s + n0);
                #pragma unroll
                for (int rr = 0; rr < 2; rr++) {
                    const int m = m0 + 16 * mg + 8 * rr + hRow;
                    const int p = m >> 15, e = m & (E_ - 1);
                    size_t orow = (size_t)N0_ + ((size_t)p << 16) + 2u * (size_t)e + (size_t)ng;
                    float2 v;
                    v.x = c2[j * 4 + 2 * rr + 0] + bb.x;
                    v.y = c2[j * 4 + 2 * rr + 1] + bb.y;
                    *(float2*)(out + orow * 64 + f) = v;
                }
            }
        }
    }
}

// ---------------- edge / attr / event fills ----------------
__global__ void copy_old_edges_kernel(const int* __restrict__ ei,
                                      const int* __restrict__ ea,
                                      float* __restrict__ out)
{
    int i = blockIdx.x * blockDim.x + threadIdx.x;
    if (i < NE_OLD_) {
        out[EI_OFF_ + i]                   = (float)ei[i];
        out[EI_OFF_ + (size_t)NE_TOT_ + i] = (float)ei[NE_OLD_ + i];
        out[EA_OFF_ + i]                   = (float)ea[i];
    }
}

__global__ void new_edges_kernel(float* __restrict__ out)
{
    int i = blockIdx.x * blockDim.x + threadIdx.x;
    if (i >= NE_NEW_) return;
    int p   = i >> 18;
    int rem = i & 262143;
    int dm1 = rem >> 16;
    int j   = rem & 65535;
    int e   = j & (E_ - 1);
    int anc = E_ * ((8 >> dm1) - 1);
    int src = anc + (p >> dm1) * E_ + e;
    int tgt = N0_ + (p << 16) + j;
    out[EI_OFF_ + NE_OLD_ + i]                   = (float)src;
    out[EI_OFF_ + (size_t)NE_TOT_ + NE_OLD_ + i] = (float)tgt;
    out[EA_OFF_ + NE_OLD_ + i]                   = (float)(dm1 + 1);
}

__global__ void event_kernel(const int* __restrict__ ev, float* __restrict__ out)
{
    int i = blockIdx.x * blockDim.x + threadIdx.x;
    if (i < NNODES_) {
        float v = (i < N0_) ? (float)ev[i] : (float)((i - N0_) & (E_ - 1));
        out[EV_OFF_ + i] = v;
    }
}

// ---------------- launch ----------------
extern "C" void kernel_launch(void* const* d_in, const int* in_sizes, int n_in,
                              void* d_out, int out_size)
{
    const float* x  = (const float*)d_in[0];
    const int*   ei = (const int*)  d_in[1];
    const int*   ea = (const int*)  d_in[2];
    const int*   ev = (const int*)  d_in[3];
    const float* g  = (const float*)d_in[4];
    const float* W1 = (const float*)d_in[5];
    const float* b1 = (const float*)d_in[6];
    const float* W2 = (const float*)d_in[7];
    const float* b2 = (const float*)d_in[8];
    float* out = (float*)d_out;

    static cudaStream_t s_side = nullptr;
    static cudaEvent_t ev_fork = nullptr, ev_join = nullptr;
    if (s_side == nullptr) {
        cudaStreamCreateWithFlags(&s_side, cudaStreamNonBlocking);
        cudaEventCreateWithFlags(&ev_fork, cudaEventDisableTiming);
        cudaEventCreateWithFlags(&ev_join, cudaEventDisableTiming);
    }

    // fork: copy + fills on side stream, concurrent with prep + MLP
    cudaEventRecord(ev_fork, 0);
    cudaStreamWaitEvent(s_side, ev_fork, 0);

    cudaMemcpyAsync(out, x, (size_t)N0_ * 64 * sizeof(float),
                    cudaMemcpyDeviceToDevice, s_side);
    copy_old_edges_kernel<<<(NE_OLD_ + 255) / 256, 256, 0, s_side>>>(ei, ea, out);
    new_edges_kernel<<<(NE_NEW_ + 255) / 256, 256, 0, s_side>>>(out);
    event_kernel<<<(NNODES_ + 255) / 256, 256, 0, s_side>>>(ev, out);
    cudaEventRecord(ev_join, s_side);

    // main stream: weight prep (+ ticket reset) then persistent MLP
    prep_w1_kernel<<<128, 256>>>(W1);
    prep_w2_kernel<<<128, 256>>>(W2);

    cudaFuncSetAttribute(mlp_mma_kernel, cudaFuncAttributeMaxDynamicSharedMemorySize, SM_SZ);
    mlp_mma_kernel<<<152, NTHREADS, SM_SZ>>>(x, g, b1, b2, out);

    // join
    cudaStreamWaitEvent(0, ev_join, 0);
}

// round 8
// speedup vs baseline: 1.1819x; 1.1617x over previous
#include <cuda_runtime.h>
#include <cuda_fp16.h>
#include <cstdint>

// ---------------- problem constants ----------------
#define E_      32768
#define N0_     (15 * E_)
#define NTILES_ 2048                  // 262144 MLP rows / 128
#define NE_OLD_ 1114112
#define NE_NEW_ 2097152
#define NE_TOT_ (NE_OLD_ + NE_NEW_)
#define NNODES_ (31 * E_)

#define EI_OFF_ ((size_t)NNODES_ * 64)
#define EA_OFF_ (EI_OFF_ + 2ull * NE_TOT_)
#define EV_OFF_ (EA_OFF_ + (size_t)NE_TOT_)

// ---------------- PTX helpers (base ISA only) ----------------
__device__ __forceinline__ uint32_t smem_u32(const void* p) {
    uint32_t a;
    asm("{ .reg .u64 t; cvta.to.shared.u64 t, %1; cvt.u32.u64 %0, t; }" : "=r"(a) : "l"(p));
    return a;
}

#define CPA16(dst, src) asm volatile("cp.async.cg.shared.global [%0], [%1], 16;" :: "r"(dst), "l"(src) : "memory")
#define CPA_COMMIT()    asm volatile("cp.async.commit_group;" ::: "memory")
#define CPA_WAIT(n)     asm volatile("cp.async.wait_group %0;" :: "n"(n) : "memory")
#define PREF_L2(p)      asm volatile("prefetch.global.L2 [%0];" :: "l"(p))

#define LDSM4(r0, r1, r2, r3, a)                                                   \
    asm volatile("ldmatrix.sync.aligned.m8n8.x4.shared.b16 {%0,%1,%2,%3}, [%4];"   \
        : "=r"(r0), "=r"(r1), "=r"(r2), "=r"(r3) : "r"(a))

#define MMA_F16(d, a0, a1, a2, a3, b0, b1)                                         \
    asm volatile("mma.sync.aligned.m16n8k16.row.col.f32.f16.f16.f32 "              \
        "{%0,%1,%2,%3}, {%4,%5,%6,%7}, {%8,%9}, {%0,%1,%2,%3};"                    \
        : "+f"((d)[0]), "+f"((d)[1]), "+f"((d)[2]), "+f"((d)[3])                   \
        : "r"(a0), "r"(a1), "r"(a2), "r"(a3), "r"(b0), "r"(b1))

__device__ __forceinline__ uint32_t h2u(__half2 h) {
    return *reinterpret_cast<uint32_t*>(&h);
}

// ---------------- device scratch ----------------
__device__ __align__(16) unsigned char glW1[36864];       // [h][128n][144B], k=0..63 (x part)
__device__ __align__(16) unsigned char glW2[2 * 34816];   // [kh][128n][272B]
__device__ __align__(16) unsigned char glGB[(size_t)E_ * 512];  // GB = G @ W1bot, fp16 [E][256]
__device__ int g_ticket;

// ============================================================================
// gbprep: GB = g @ W1[64:128] (E x 256), + prep glW1/glW2 images + ticket reset
// grid 256 x 512 thr; CTA cb computes g rows [128cb, 128cb+128)
// ============================================================================
#define GBP_SM_A 0
#define GBP_SM_W 18432
#define GBP_SM_SZ 55296

__global__ void __launch_bounds__(512, 1)
gbprep_kernel(const float* __restrict__ g, const float* __restrict__ W1,
              const float* __restrict__ W2)
{
    extern __shared__ __align__(128) unsigned char sm[];
    const int t = threadIdx.x, cb = blockIdx.x;
    const int wid = t >> 5, l = t & 31;
    const uint32_t sb = smem_u32(sm);

    if (cb == 0 && t == 0) g_ticket = 0;

    // prep weight images for the MLP kernel
    if (cb < 32) {
        int i = cb * 512 + t;                 // [0,16384): W1 x-part (k 0..63)
        int k = i >> 8, n = i & 255;
        uint32_t off = (uint32_t)(n >> 7) * 18432u + (uint32_t)(n & 127) * 144u + (uint32_t)k * 2u;
        *(__half*)(glW1 + off) = __float2half(W1[k * 256 + n]);
    } else if (cb < 96) {
        int i = (cb - 32) * 512 + t;          // [0,32768): W2
        int k = i >> 7, n = i & 127;
        uint32_t off = (uint32_t)(k >> 7) * 34816u + (uint32_t)n * 272u + (uint32_t)(k & 127) * 2u;
        *(__half*)(glW2 + off) = __float2half(W2[k * 128 + n]);
    }

    // W1 bottom (k 64..127) -> smem [nh][128n][144B]
    for (int i = t; i < 16384; i += 512) {
        int kk = i >> 8, n = i & 255;
        uint32_t off = (uint32_t)(n >> 7) * 18432u + (uint32_t)(n & 127) * 144u + (uint32_t)kk * 2u;
        *(__half*)(sm + GBP_SM_W + off) = __float2half(W1[(64 + kk) * 256 + n]);
    }
    // g tile
    {
        const int r = t >> 2, q = t & 3;
        const float4* src = (const float4*)(g + ((size_t)(cb * 128 + r)) * 64 + 16 * q);
        unsigned char* Ap = sm + GBP_SM_A + (size_t)r * 144 + (size_t)q * 32;
        #pragma unroll
        for (int i = 0; i < 4; i++) {
            float4 v = src[i];
            *(uint2*)(Ap + i * 8) = make_uint2(h2u(__float22half2_rn(make_float2(v.x, v.y))),
                                               h2u(__float22half2_rn(make_float2(v.z, v.w))));
        }
    }
    __syncthreads();

    const int mg = wid & 7, ng = wid >> 3;      // 16 rows x 128 cols per warp
    const uint32_t off144 = (uint32_t)(l & 15) * 144u + (uint32_t)((l >> 4) << 4);
    const uint32_t aB = sb + GBP_SM_A + (uint32_t)(16 * mg) * 144u + off144;
    const uint32_t wB = sb + GBP_SM_W + (uint32_t)ng * 18432u + off144;

    float c[64];
    #pragma unroll
    for (int i = 0; i < 64; i++) c[i] = 0.0f;

    #pragma unroll
    for (int kc = 0; kc < 4; kc++) {
        uint32_t a0, a1, a2, a3;
        LDSM4(a0, a1, a2, a3, aB + kc * 32);
        #pragma unroll
        for (int hf = 0; hf < 2; hf++) {
            uint32_t bb[16];
            #pragma unroll
            for (int b2 = 0; b2 < 4; b2++)
                LDSM4(bb[4 * b2], bb[4 * b2 + 1], bb[4 * b2 + 2], bb[4 * b2 + 3],
                      wB + (uint32_t)(4 * hf + b2) * (16u * 144u) + kc * 32);
            #pragma unroll
            for (int b2 = 0; b2 < 4; b2++) {
                int j0 = 2 * (4 * hf + b2);
                MMA_F16(c + j0 * 4,       a0, a1, a2, a3, bb[4 * b2],     bb[4 * b2 + 2]);
                MMA_F16(c + (j0 + 1) * 4, a0, a1, a2, a3, bb[4 * b2 + 1], bb[4 * b2 + 3]);
            }
        }
    }

    // store fp16 GB
    {
        const int hRow = l >> 2, hCol2 = (l & 3) << 1;
        uint32_t* GB32 = (uint32_t*)glGB;
        #pragma unroll
        for (int j = 0; j < 16; j++) {
            int col = 128 * ng + 8 * j + hCol2;
            #pragma unroll
            for (int rr = 0; rr < 2; rr++) {
                int row = cb * 128 + 16 * mg + 8 * rr + hRow;
                GB32[(size_t)row * 128 + (col >> 1)] =
                    h2u(__floats2half2_rn(c[j * 4 + 2 * rr + 0], c[j * 4 + 2 * rr + 1]));
            }
        }
    }
}

// ============================================================================
// persistent MLP: GEMM1 K=64 (x only) + GB seed, GEMM2 K=256
// ============================================================================
#define SM_A    0                         // 128 x 144
#define SM_W1   18432                     // [2][128][144] = 36864
#define SM_W2   (18432 + 36864)           // 55296 : [2][128][272] = 69632
#define SM_H    (55296 + 69632)           // 124928: 128 x 272 = 34816
#define SM_B1   (124928 + 34816)          // 159744: 256 floats
#define SM_B2   (SM_B1 + 1024)
#define SM_SZ   (SM_B2 + 512)             // 161280

__device__ __forceinline__ void build_A(unsigned char* Abuf, int m0,
                                        const float* __restrict__ x, int t)
{
    const int r = t >> 2, q = t & 3;
    const float4* src = (const float4*)(x + ((size_t)(7 * E_) + (size_t)(m0 + r)) * 64 + 16 * q);
    unsigned char* Ap = Abuf + (size_t)r * 144 + (size_t)q * 32;
    #pragma unroll
    for (int i = 0; i < 4; i++) {
        float4 v = src[i];
        *(uint2*)(Ap + i * 8) = make_uint2(h2u(__float22half2_rn(make_float2(v.x, v.y))),
                                           h2u(__float22half2_rn(make_float2(v.z, v.w))));
    }
}

__global__ void __launch_bounds__(512, 1)
mlp_mma_kernel(const float* __restrict__ x,
               const float* __restrict__ b1, const float* __restrict__ b2,
               float* __restrict__ out)
{
    extern __shared__ __align__(128) unsigned char sm[];
    __shared__ int s_tile[2];

    const int t = threadIdx.x;
    const int wid = t >> 5, l = t & 31;
    const int mg = wid & 7;            // rows [16mg, 16mg+16)
    const int ng = wid >> 3;           // cols [64ng, 64ng+64)
    const uint32_t sb = smem_u32(sm);

    // weights resident
    for (int i = t; i < 2304; i += 512) CPA16(sb + SM_W1 + (uint32_t)i * 16, glW1 + (size_t)i * 16);
    for (int i = t; i < 4352; i += 512) CPA16(sb + SM_W2 + (uint32_t)i * 16, glW2 + (size_t)i * 16);
    CPA_COMMIT();

    if (t < 256) ((float*)(sm + SM_B1))[t] = b1[t];
    else if (t < 384) ((float*)(sm + SM_B2))[t - 256] = b2[t - 256];

    const uint32_t off144 = (uint32_t)(l & 15) * 144u + (uint32_t)((l >> 4) << 4);
    const uint32_t off272 = (uint32_t)(l & 15) * 272u + (uint32_t)((l >> 4) << 4);
    const uint32_t aBase = sb + SM_A + (uint32_t)(16 * mg) * 144u + off144;
    const uint32_t hBase = sb + SM_H + (uint32_t)(16 * mg) * 272u + off272;
    const float* b1s = (const float*)(sm + SM_B1);
    const float* b2s = (const float*)(sm + SM_B2);
    const uint32_t* GB32 = (const uint32_t*)glGB;

    const int hRow = l >> 2;
    const int hCol2 = (l & 3) << 1;

    // prologue
    if (t == 0) s_tile[0] = atomicAdd(&g_ticket, 1);
    __syncthreads();
    int tile = s_tile[0];
    int slot = 0;
    if (tile < NTILES_) build_A(sm + SM_A, tile << 7, x, t);
    CPA_WAIT(0);
    __syncthreads();                      // A + weights + biases visible

    while (tile < NTILES_) {
        if (t == 0) s_tile[slot ^ 1] = atomicAdd(&g_ticket, 1);
        __syncthreads();                  // ticket + A(next from prev iter) visible
        const int next = s_tile[slot ^ 1];
        const int m0 = tile << 7;
        const int e0 = m0 & (E_ - 1);

        // L2 prefetch for next tile (x rows + GB rows)
        if (next < NTILES_) {
            const char* px = (const char*)(x + ((size_t)(7 * E_) + ((size_t)next << 7)) * 64);
            if (t < 256) PREF_L2(px + (size_t)t * 128);
            const char* pg = (const char*)glGB + (size_t)((next << 7) & (E_ - 1)) * 512;
            PREF_L2(pg + (size_t)t * 128);
        }

        float c2[32];
        #pragma unroll
        for (int i = 0; i < 32; i++) c2[i] = 0.0f;

        #pragma unroll 1
        for (int h = 0; h < 2; h++) {
            // GB fragment loads (held in regs through GEMM1; latency hidden)
            uint32_t gbv[16];
            {
                const int cb0 = 64 * h + 32 * ng + (hCol2 >> 1);
                const int rbase = e0 + 16 * mg + hRow;
                #pragma unroll
                for (int j = 0; j < 8; j++) {
                    gbv[2 * j]     = GB32[(size_t)rbase * 128 + cb0 + 4 * j];
                    gbv[2 * j + 1] = GB32[(size_t)(rbase + 8) * 128 + cb0 + 4 * j];
                }
            }

            // ---- GEMM1 half h: K=64 (x part only) ----
            float c1[32];
            #pragma unroll
            for (int i = 0; i < 32; i++) c1[i] = 0.0f;

            const uint32_t w1A = sb + SM_W1 + (uint32_t)h * 18432u + (uint32_t)(64 * ng) * 144u + off144;
            #pragma unroll
            for (int kc = 0; kc < 4; kc++) {
                uint32_t a0, a1, a2, a3;
                LDSM4(a0, a1, a2, a3, aBase + kc * 32);
                uint32_t bb[16];
                #pragma unroll
                for (int bi = 0; bi < 4; bi++)
                    LDSM4(bb[4 * bi], bb[4 * bi + 1], bb[4 * bi + 2], bb[4 * bi + 3],
                          w1A + (uint32_t)bi * (16u * 144u) + kc * 32);
                #pragma unroll
                for (int bi = 0; bi < 4; bi++) {
                    MMA_F16(c1 + (2 * bi) * 4,     a0, a1, a2, a3, bb[4 * bi],     bb[4 * bi + 2]);
                    MMA_F16(c1 + (2 * bi + 1) * 4, a0, a1, a2, a3, bb[4 * bi + 1], bb[4 * bi + 3]);
                }
            }

            __syncthreads();              // prev GEMM2 H reads done; (h==1): A fully consumed

            // ---- convert: relu(c1 + GB + b1) -> fp16 H tile ----
            #pragma unroll
            for (int j = 0; j < 8; j++) {
                const int colh = 64 * ng + 8 * j + hCol2;
                const float2 bb1 = *(const float2*)(b1s + 128 * h + colh);
                float2 f0 = __half22float2(*(__half2*)&gbv[2 * j]);
                float2 f1 = __half22float2(*(__half2*)&gbv[2 * j + 1]);
                float v0 = fmaxf(c1[j * 4 + 0] + f0.x + bb1.x, 0.0f);
                float v1 = fmaxf(c1[j * 4 + 1] + f0.y + bb1.y, 0.0f);
                float v2 = fmaxf(c1[j * 4 + 2] + f1.x + bb1.x, 0.0f);
                float v3 = fmaxf(c1[j * 4 + 3] + f1.y + bb1.y, 0.0f);
                unsigned char* hp = sm + SM_H + (size_t)(16 * mg + hRow) * 272 + (size_t)colh * 2;
                *(uint32_t*)hp             = h2u(__float22half2_rn(make_float2(v0, v1)));
                *(uint32_t*)(hp + 8 * 272) = h2u(__float22half2_rn(make_float2(v2, v3)));
            }

            // A free after the post-GEMM1(h=1) sync: build next tile's A here
            if (h == 1 && next < NTILES_) build_A(sm + SM_A, next << 7, x, t);

            __syncthreads();              // H visible

            // ---- GEMM2 half h: K=128 of 256 ----
            const uint32_t w2A = sb + SM_W2 + (uint32_t)h * 34816u + (uint32_t)(64 * ng) * 272u + off272;
            #pragma unroll 1
            for (int kc = 0; kc < 8; kc++) {
                uint32_t a0, a1, a2, a3;
                LDSM4(a0, a1, a2, a3, hBase + kc * 32);
                uint32_t bb[16];
                #pragma unroll
                for (int bi = 0; bi < 4; bi++)
                    LDSM4(bb[4 * bi], bb[4 * bi + 1], bb[4 * bi + 2], bb[4 * bi + 3],
                          w2A + (uint32_t)bi * (16u * 272u) + kc * 32);
                #pragma unroll
                for (int bi = 0; bi < 4; bi++) {
                    MMA_F16(c2 + (2 * bi) * 4,     a0, a1, a2, a3, bb[4 * bi],     bb[4 * bi + 2]);
                    MMA_F16(c2 + (2 * bi + 1) * 4, a0, a1, a2, a3, bb[4 * bi + 1], bb[4 * bi + 3]);
                }
            }
        }

        // ---- epilogue: out = c2 + b2; warp writes branch=ng ----
        #pragma unroll
        for (int j = 0; j < 8; j++) {
            const int n0 = 64 * ng + 8 * j + hCol2;
            const int f = n0 & 63;
            const float2 bb = *(const float2*)(b2s + n0);
            #pragma unroll
            for (int rr = 0; rr < 2; rr++) {
                const int m = m0 + 16 * mg + 8 * rr + hRow;
                const int p = m >> 15, e = m & (E_ - 1);
                size_t orow = (size_t)N0_ + ((size_t)p << 16) + 2u * (size_t)e + (size_t)ng;
                float2 v;
                v.x = c2[j * 4 + 2 * rr + 0] + bb.x;
                v.y = c2[j * 4 + 2 * rr + 1] + bb.y;
                *(float2*)(out + orow * 64 + f) = v;
            }
        }

        tile = next;
        slot ^= 1;
    }
}

// ---------------- edge fills (merged old+new) ----------------
#define OLD_BLKS 4352                    // NE_OLD_/256
__global__ void edges_kernel(const int* __restrict__ ei,
                             const int* __restrict__ ea,
                             float* __restrict__ out)
{
    if (blockIdx.x < OLD_BLKS) {
        int i = blockIdx.x * 256 + threadIdx.x;
        if (i < NE_OLD_) {
            out[EI_OFF_ + i]                   = (float)ei[i];
            out[EI_OFF_ + (size_t)NE_TOT_ + i] = (float)ei[NE_OLD_ + i];
            out[EA_OFF_ + i]                   = (float)ea[i];
        }
    } else {
        int i = (blockIdx.x - OLD_BLKS) * 256 + threadIdx.x;
        if (i >= NE_NEW_) return;
        int p   = i >> 18;
        int rem = i & 262143;
        int dm1 = rem >> 16;
        int j   = rem & 65535;
        int e   = j & (E_ - 1);
        int anc = E_ * ((8 >> dm1) - 1);
        int src = anc + (p >> dm1) * E_ + e;
        int tgt = N0_ + (p << 16) + j;
        out[EI_OFF_ + NE_OLD_ + i]                   = (float)src;
        out[EI_OFF_ + (size_t)NE_TOT_ + NE_OLD_ + i] = (float)tgt;
        out[EA_OFF_ + NE_OLD_ + i]                   = (float)(dm1 + 1);
    }
}

__global__ void event_kernel(const int* __restrict__ ev, float* __restrict__ out)
{
    int i = blockIdx.x * blockDim.x + threadIdx.x;
    if (i < NNODES_) {
        float v = (i < N0_) ? (float)ev[i] : (float)((i - N0_) & (E_ - 1));
        out[EV_OFF_ + i] = v;
    }
}

// ---------------- launch ----------------
extern "C" void kernel_launch(void* const* d_in, const int* in_sizes, int n_in,
                              void* d_out, int out_size)
{
    const float* x  = (const float*)d_in[0];
    const int*   ei = (const int*)  d_in[1];
    const int*   ea = (const int*)  d_in[2];
    const int*   ev = (const int*)  d_in[3];
    const float* g  = (const float*)d_in[4];
    const float* W1 = (const float*)d_in[5];
    const float* b1 = (const float*)d_in[6];
    const float* W2 = (const float*)d_in[7];
    const float* b2 = (const float*)d_in[8];
    float* out = (float*)d_out;

    static cudaStream_t s_side = nullptr;
    static cudaEvent_t ev_fork = nullptr, ev_join = nullptr;
    if (s_side == nullptr) {
        cudaStreamCreateWithFlags(&s_side, cudaStreamNonBlocking);
        cudaEventCreateWithFlags(&ev_fork, cudaEventDisableTiming);
        cudaEventCreateWithFlags(&ev_join, cudaEventDisableTiming);
    }

    // fork: copy + fills on side stream
    cudaEventRecord(ev_fork, 0);
    cudaStreamWaitEvent(s_side, ev_fork, 0);

    cudaMemcpyAsync(out, x, (size_t)N0_ * 64 * sizeof(float),
                    cudaMemcpyDeviceToDevice, s_side);
    edges_kernel<<<OLD_BLKS + NE_NEW_ / 256, 256, 0, s_side>>>(ei, ea, out);
    event_kernel<<<(NNODES_ + 255) / 256, 256, 0, s_side>>>(ev, out);
    cudaEventRecord(ev_join, s_side);

    // main stream: GB precompute (+ weight images + ticket reset) then MLP
    cudaFuncSetAttribute(gbprep_kernel, cudaFuncAttributeMaxDynamicSharedMemorySize, GBP_SM_SZ);
    gbprep_kernel<<<256, 512, GBP_SM_SZ>>>(g, W1, W2);

    cudaFuncSetAttribute(mlp_mma_kernel, cudaFuncAttributeMaxDynamicSharedMemorySize, SM_SZ);
    mlp_mma_kernel<<<152, 512, SM_SZ>>>(x, b1, b2, out);

    // join
    cudaStreamWaitEvent(0, ev_join, 0);
}